// round 7
// baseline (speedup 1.0000x reference)
#include <cuda_runtime.h>
#include <cuda_bf16.h>
#include <cstdint>

typedef __nv_bfloat16 bf16;

// tcgen05 is only legal in an arch-specific (compute_103a) device pass.
#if defined(__CUDA_ARCH__) && (__CUDA_ARCH__ == 1030) && \
    (defined(__CUDA_ARCH_FEAT_SM103_ALL) || defined(__CUDA_ARCH_FEAT_SM100_ALL))
#define TC_OK 1
#else
#define TC_OK 0
#endif

#define DIMV 768
#define HIDV 2048
#define TOKV 4096
#define NEXP 8
#define MAXGRP 24            // 256-row expert groups
#define NTILE (MAXGRP*2)     // 128-row tiles (HM path)
#define MAXROWS (MAXGRP*256) // 6144

#define BM 128
#define KC 32           // tcgen05 stage K elems (64B rows, SW64)
#define BK 32           // HMMA stage K elems
#define SROW 40         // HMMA smem row pitch (bf16)

// ------------------------- device scratch ---------------------------------
__device__ bf16 gW1h[(size_t)NEXP*HIDV*DIMV];
__device__ bf16 gW1l[(size_t)NEXP*HIDV*DIMV];
__device__ bf16 gW2h[(size_t)NEXP*HIDV*DIMV];
__device__ bf16 gW2l[(size_t)NEXP*HIDV*DIMV];
__device__ bf16 gW3h[(size_t)NEXP*DIMV*HIDV];
__device__ bf16 gW3l[(size_t)NEXP*DIMV*HIDV];
__device__ bf16 gXh[(size_t)MAXROWS*DIMV];
__device__ bf16 gXl[(size_t)MAXROWS*DIMV];
__device__ bf16 gUh[(size_t)MAXROWS*HIDV];
__device__ bf16 gUl[(size_t)MAXROWS*HIDV];
__device__ int   gTokE[TOKV];
__device__ float gP[TOKV];
__device__ int   gRowTok[MAXROWS];
__device__ int   gGrpE[MAXGRP];

// ------------------------- common helpers ----------------------------------
__device__ __forceinline__ uint32_t smem_u32(const void* p) {
    uint32_t a;
    asm("{ .reg .u64 t; cvta.to.shared.u64 t, %1; cvt.u32.u64 %0, t; }" : "=r"(a) : "l"(p));
    return a;
}
__device__ __forceinline__ void cp16(uint32_t s, const void* g) {
    asm volatile("cp.async.cg.shared.global [%0], [%1], 16;\n" :: "r"(s), "l"(g));
}
__device__ __forceinline__ void cpcommit() { asm volatile("cp.async.commit_group;\n"); }
__device__ __forceinline__ void split2(float v, bf16& h, bf16& l) {
    h = __float2bfloat16(v);
    l = __float2bfloat16(v - __bfloat162float(h));
}
__device__ __forceinline__ void mma_bf16(float* c, const unsigned* a, const unsigned* b) {
    asm volatile(
        "mma.sync.aligned.m16n8k16.row.col.f32.bf16.bf16.f32 "
        "{%0,%1,%2,%3},{%4,%5,%6,%7},{%8,%9},{%0,%1,%2,%3};\n"
        : "+f"(c[0]), "+f"(c[1]), "+f"(c[2]), "+f"(c[3])
        : "r"(a[0]), "r"(a[1]), "r"(a[2]), "r"(a[3]), "r"(b[0]), "r"(b[1]));
}

#define SWZ64(x) ((x) ^ (((x) >> 3) & 0x30))

// ------------------------- tcgen05 helpers (bodies arch-gated) -------------
__device__ __forceinline__ uint32_t elect1() {
    uint32_t p = 0;
#if TC_OK
    asm volatile("{ .reg .pred p; elect.sync _|p, 0xFFFFFFFF; selp.b32 %0,1,0,p; }" : "=r"(p));
#endif
    return p;
}
__device__ __forceinline__ uint64_t desc64(uint32_t addr) {
    // SW64 layout: layout_type=4, version=1 (Blackwell), SBO=32 (512B), LBO=1 (16B)
    const uint64_t base = (uint64_t(4) << 61) | (uint64_t(1) << 46)
                        | (uint64_t(32) << 32) | (uint64_t(1) << 16);
    return base | ((uint64_t)(addr >> 4) & 0x3FFF);
}
// kind::f16 idesc: dtype=F32(1<<4), atype=BF16(1<<7), btype=BF16(1<<10),
// N/8<<17, M/16<<24.  M=128, N=128 -> 0x8200490
#define IDESC 0x8200490u

__device__ __forceinline__ void mma_ss(uint32_t d, uint64_t ad, uint64_t bd, uint32_t en) {
#if TC_OK
    asm volatile(
        "{\n .reg .pred p;\n setp.ne.u32 p, %4, 0;\n"
        " tcgen05.mma.cta_group::1.kind::f16 [%0], %1, %2, %3, {%5,%5,%5,%5}, p;\n}"
        :: "r"(d), "l"(ad), "l"(bd), "r"(IDESC), "r"(en), "r"(0u) : "memory");
#endif
}
__device__ __forceinline__ void mma_commit(uint32_t mbar) {
#if TC_OK
    asm volatile(
        "tcgen05.commit.cta_group::1.mbarrier::arrive::one.shared::cluster.b64 [%0];"
        :: "r"(mbar) : "memory");
#endif
}
__device__ __forceinline__ void cp_arrive(uint32_t mbar) {
#if TC_OK
    // .noinc is load-bearing: the default form increments the pending count at
    // execution (self-balancing) and the barrier would NEVER flip against a
    // fixed init count -> R6 deadlock. .noinc arrives against the init count.
    asm volatile("cp.async.mbarrier.arrive.noinc.shared::cta.b64 [%0];" :: "r"(mbar) : "memory");
#endif
}
__device__ __forceinline__ void mbar_init(uint32_t a, uint32_t c) {
#if TC_OK
    asm volatile("mbarrier.init.shared.b64 [%0], %1;" :: "r"(a), "r"(c) : "memory");
#endif
}
__device__ __forceinline__ void mbar_inval(uint32_t a) {
#if TC_OK
    asm volatile("mbarrier.inval.shared.b64 [%0];" :: "r"(a) : "memory");
#endif
}
__device__ __forceinline__ void mbar_wait(uint32_t a, uint32_t ph) {
#if TC_OK
    uint32_t ok = 0;
    while (!ok) {
        asm volatile(
            "{\n .reg .pred P;\n"
            " mbarrier.try_wait.parity.acquire.cta.shared::cta.b64 P, [%1], %2, 0x989680;\n"
            " selp.b32 %0, 1, 0, P;\n}"
            : "=r"(ok) : "r"(a), "r"(ph) : "memory");
    }
#endif
}
__device__ __forceinline__ void tmem_alloc(uint32_t smem_ptr, uint32_t ncols) {
#if TC_OK
    asm volatile("tcgen05.alloc.cta_group::1.sync.aligned.shared::cta.b32 [%0], %1;"
                 :: "r"(smem_ptr), "r"(ncols) : "memory");
#endif
}
__device__ __forceinline__ void tmem_dealloc(uint32_t tmem, uint32_t ncols) {
#if TC_OK
    asm volatile("tcgen05.relinquish_alloc_permit.cta_group::1.sync.aligned;");
    asm volatile("tcgen05.dealloc.cta_group::1.sync.aligned.b32 %0, %1;" :: "r"(tmem), "r"(ncols));
#endif
}
__device__ __forceinline__ void ldtm32(uint32_t* r, uint32_t ta) {
#if TC_OK
    asm volatile(
        "tcgen05.ld.sync.aligned.32x32b.x32.b32 "
        "{%0,%1,%2,%3,%4,%5,%6,%7,%8,%9,%10,%11,%12,%13,%14,%15,"
        "%16,%17,%18,%19,%20,%21,%22,%23,%24,%25,%26,%27,%28,%29,%30,%31}, [%32];"
        : "=r"(r[0]), "=r"(r[1]), "=r"(r[2]), "=r"(r[3]), "=r"(r[4]), "=r"(r[5]),
          "=r"(r[6]), "=r"(r[7]), "=r"(r[8]), "=r"(r[9]), "=r"(r[10]), "=r"(r[11]),
          "=r"(r[12]), "=r"(r[13]), "=r"(r[14]), "=r"(r[15]), "=r"(r[16]), "=r"(r[17]),
          "=r"(r[18]), "=r"(r[19]), "=r"(r[20]), "=r"(r[21]), "=r"(r[22]), "=r"(r[23]),
          "=r"(r[24]), "=r"(r[25]), "=r"(r[26]), "=r"(r[27]), "=r"(r[28]), "=r"(r[29]),
          "=r"(r[30]), "=r"(r[31])
        : "r"(ta));
#endif
}
__device__ __forceinline__ void tm_wait_ld() {
#if TC_OK
    asm volatile("tcgen05.wait::ld.sync.aligned;" ::: "memory");
#endif
}
__device__ __forceinline__ void tm_fence_after() {
#if TC_OK
    asm volatile("tcgen05.fence::after_thread_sync;" ::: "memory");
#endif
}
__device__ __forceinline__ void fence_async_smem() {
#if TC_OK
    asm volatile("fence.proxy.async.shared::cta;" ::: "memory");
#endif
}

// ------------------------- router ------------------------------------------
__global__ void router_k(const float* __restrict__ x,
                         const float* __restrict__ rw,
                         const float* __restrict__ rb) {
    int wid  = (blockIdx.x * blockDim.x + threadIdx.x) >> 5;
    int lane = threadIdx.x & 31;
    if (wid >= TOKV) return;
    const float* xr = x + (size_t)wid * DIMV;
    float acc[NEXP];
#pragma unroll
    for (int e = 0; e < NEXP; e++) acc[e] = 0.f;
    for (int k = lane; k < DIMV; k += 32) {
        float xv = xr[k];
        const float* w = rw + k * NEXP;
#pragma unroll
        for (int e = 0; e < NEXP; e++) acc[e] += xv * w[e];
    }
#pragma unroll
    for (int off = 16; off; off >>= 1)
#pragma unroll
        for (int e = 0; e < NEXP; e++)
            acc[e] += __shfl_xor_sync(0xffffffffu, acc[e], off);
    if (lane == 0) {
        float l[NEXP];
        float m = -1e30f; int mi = 0;
#pragma unroll
        for (int e = 0; e < NEXP; e++) {
            l[e] = acc[e] + rb[e];
            if (l[e] > m) { m = l[e]; mi = e; }
        }
        float s = 0.f;
#pragma unroll
        for (int e = 0; e < NEXP; e++) s += expf(l[e] - m);
        gTokE[wid] = mi;
        gP[wid] = 1.f / s;
    }
}

// ------------------------- plan: 256-row expert groups ----------------------
__global__ void plan_k() {
    __shared__ int cnt[NEXP], cur[NEXP], base[NEXP];
    int tid = threadIdx.x;
    if (tid < NEXP) { cnt[tid] = 0; cur[tid] = 0; }
    __syncthreads();
    for (int t = tid; t < TOKV; t += blockDim.x) atomicAdd(&cnt[gTokE[t]], 1);
    __syncthreads();
    if (tid == 0) {
        int acc = 0, gc = 0;
        for (int e = 0; e < NEXP; e++) {
            base[e] = acc;
            int ng = (cnt[e] + 255) >> 8;
            for (int i = 0; i < ng && gc < MAXGRP; i++) gGrpE[gc++] = e;
            acc += ng * 256;
        }
        for (; gc < MAXGRP; gc++) gGrpE[gc] = 0;
    }
    __syncthreads();
    for (int r = tid; r < MAXROWS; r += blockDim.x) gRowTok[r] = -1;
    __syncthreads();
    for (int t = tid; t < TOKV; t += blockDim.x) {
        int e = gTokE[t];
        int s = atomicAdd(&cur[e], 1);
        gRowTok[base[e] + s] = t;
    }
}

// ---------------- weight transpose + bf16 split (coalesced) ----------------
// src [E][R][C] f32 -> dst hi/lo [E][C][R] bf16
__global__ void tsplit_k(const float* __restrict__ src, int R, int C, int which) {
    __shared__ float tile[64][65];
    bf16 *dh, *dl;
    if (which == 0)      { dh = gW1h; dl = gW1l; }
    else if (which == 1) { dh = gW2h; dl = gW2l; }
    else                 { dh = gW3h; dl = gW3l; }
    int e = blockIdx.z;
    int c0 = blockIdx.x * 64, r0 = blockIdx.y * 64;
    int tid = threadIdx.x;
    const float* s = src + (size_t)e * R * C;
#pragma unroll
    for (int i = 0; i < 16; i++) {
        int idx = i * 256 + tid;
        int r = idx >> 6, c = idx & 63;
        tile[r][c] = s[(size_t)(r0 + r) * C + c0 + c];
    }
    __syncthreads();
    bf16* dhp = dh + (size_t)e * C * R;
    bf16* dlp = dl + (size_t)e * C * R;
#pragma unroll
    for (int i = 0; i < 8; i++) {
        int idx = i * 256 + tid;
        int c = idx >> 5, rp = idx & 31, r = rp * 2;
        float v0 = tile[r][c], v1 = tile[r + 1][c];
        bf16 h0, l0, h1, l1;
        split2(v0, h0, l0);
        split2(v1, h1, l1);
        __nv_bfloat162 vh; vh.x = h0; vh.y = h1;
        __nv_bfloat162 vl; vl.x = l0; vl.y = l1;
        size_t o = (size_t)(c0 + c) * R + r0 + r;
        *(__nv_bfloat162*)(dhp + o) = vh;
        *(__nv_bfloat162*)(dlp + o) = vl;
    }
}

// ------------------------- gather X + split --------------------------------
__global__ void gather_k(const float* __restrict__ x) {
    int row = blockIdx.x;
    int tok = gRowTok[row];
    for (int k = threadIdx.x; k < DIMV; k += blockDim.x) {
        float v = (tok >= 0) ? x[(size_t)tok * DIMV + k] : 0.f;
        bf16 h, l; split2(v, h, l);
        gXh[(size_t)row * DIMV + k] = h;
        gXl[(size_t)row * DIMV + k] = l;
    }
}

// ===================== tcgen05 GEMM1: 3-stage mbarrier pipeline ============
// smem: [0] tmem ptr, [16..40) full[3], [48..72) empty[3], [80] done
// stage (64KB): A0h A0l A1h A1l B1h B1l B2h B2l, 8KB each
#define G1_STG 65536
#define G1_SMEM (1024 + 3*G1_STG)

#if TC_OK
__device__ __forceinline__ void g1_fill(uint32_t sb, int buf, int kc,
                                        int grp, int e, int nb0, int tid) {
    uint32_t st = sb + 1024 + buf * G1_STG;
#pragma unroll
    for (int i = 0; i < 8; i++) {           // A: 4 regions x 512 chunks
        int id = i * 256 + tid;
        int reg = id >> 9, c2 = id & 511;
        int row = c2 >> 2, cb = c2 & 3;
        uint32_t off = SWZ64((uint32_t)(row * 64 + cb * 16));
        const bf16* srcA = (reg & 1) ? gXl : gXh;
        const bf16* g = srcA + ((size_t)(grp * 256 + (reg >> 1) * 128 + row) * DIMV + kc + cb * 8);
        cp16(st + reg * 8192 + off, g);
    }
#pragma unroll
    for (int i = 0; i < 8; i++) {           // B: 4 regions x 512 chunks
        int id = i * 256 + tid;
        int reg = id >> 9, c2 = id & 511;
        int row = c2 >> 2, cb = c2 & 3;
        uint32_t off = SWZ64((uint32_t)(row * 64 + cb * 16));
        const bf16* srcB = (reg == 0) ? gW1h : (reg == 1) ? gW1l : (reg == 2) ? gW2h : gW2l;
        const bf16* g = srcB + ((size_t)e * HIDV + nb0 + row) * DIMV + kc + cb * 8;
        cp16(st + 32768 + reg * 8192 + off, g);
    }
}
#endif

__global__ __launch_bounds__(256) void gemm1_tc() {
#if TC_OK
    extern __shared__ char smem[];
    uint32_t sb = smem_u32(smem);
    int tid = threadIdx.x, wid = tid >> 5, lane = tid & 31;
    int grp = blockIdx.y, nb0 = blockIdx.x * 128;
    int e = gGrpE[grp];

    if (wid == 0) tmem_alloc(sb, 512);
    if (tid == 0) {
#pragma unroll
        for (int i = 0; i < 3; i++) {
            mbar_init(sb + 16 + i * 8, 256);  // full: one arrive per thread
            mbar_init(sb + 48 + i * 8, 1);    // empty: tcgen05.commit
        }
        mbar_init(sb + 80, 1);                // done
    }
    __syncthreads();
    uint32_t tmem;
    asm volatile("ld.shared.b32 %0, [%1];" : "=r"(tmem) : "r"(sb));

    const int NS = DIMV / KC;  // 24
    for (int s = 0; s < NS; s++) {
        int b = s % 3;
        if (s >= 3) mbar_wait(sb + 48 + b * 8, ((s - 3) / 3) & 1);
        g1_fill(sb, b, s * KC, grp, e, nb0, tid);
        cp_arrive(sb + 16 + b * 8);
        if (wid == 0) {
            mbar_wait(sb + 16 + b * 8, (s / 3) & 1);
            fence_async_smem();
            if (elect1()) {
                uint32_t st = sb + 1024 + b * G1_STG;
                uint64_t dA[2][2];
                dA[0][0] = desc64(st);          dA[0][1] = desc64(st + 8192);
                dA[1][0] = desc64(st + 16384);  dA[1][1] = desc64(st + 24576);
                uint64_t b1h = desc64(st + 32768), b1l = desc64(st + 40960);
                uint64_t b2h = desc64(st + 49152), b2l = desc64(st + 57344);
#pragma unroll
                for (int t = 0; t < 2; t++) {
                    uint32_t D1 = tmem + t * 256, D2 = tmem + t * 256 + 128;
#pragma unroll
                    for (int k = 0; k < 2; k++) {
                        uint32_t en = (s == 0 && k == 0) ? 0u : 1u;
                        uint64_t k2 = (uint64_t)(k * 2);
                        mma_ss(D1, dA[t][0] + k2, b1h + k2, en);
                        mma_ss(D1, dA[t][0] + k2, b1l + k2, 1u);
                        mma_ss(D1, dA[t][1] + k2, b1h + k2, 1u);
                        mma_ss(D2, dA[t][0] + k2, b2h + k2, en);
                        mma_ss(D2, dA[t][0] + k2, b2l + k2, 1u);
                        mma_ss(D2, dA[t][1] + k2, b2h + k2, 1u);
                    }
                }
                mma_commit(sb + 48 + b * 8);
            }
        }
    }
    if (wid == 0) {
        if (elect1()) mma_commit(sb + 80);
    }
    mbar_wait(sb + 80, 0);
    tm_fence_after();

    {
        int t = wid >> 2;
        uint32_t T = tmem + t * 256;
        int grow = grp * 256 + t * 128 + (wid & 3) * 32 + lane;
        bf16* dh = gUh + (size_t)grow * HIDV + nb0;
        bf16* dl = gUl + (size_t)grow * HIDV + nb0;
#pragma unroll
        for (int p = 0; p < 4; p++) {
            uint32_t r1[32], r2[32];
            ldtm32(r1, T + p * 32);
            ldtm32(r2, T + 128 + p * 32);
            tm_wait_ld();
#pragma unroll
            for (int j = 0; j < 32; j += 2) {
                float h1a = __uint_as_float(r1[j]),     h2a = __uint_as_float(r2[j]);
                float h1b = __uint_as_float(r1[j + 1]), h2b = __uint_as_float(r2[j + 1]);
                float ua = h1a * (1.f / (1.f + expf(-h1a))) * h2a;
                float ub = h1b * (1.f / (1.f + expf(-h1b))) * h2b;
                bf16 ha, la, hb, lb;
                split2(ua, ha, la);
                split2(ub, hb, lb);
                __nv_bfloat162 vh; vh.x = ha; vh.y = hb;
                __nv_bfloat162 vl; vl.x = la; vl.y = lb;
                *(__nv_bfloat162*)(dh + p * 32 + j) = vh;
                *(__nv_bfloat162*)(dl + p * 32 + j) = vl;
            }
        }
    }
    __syncthreads();
    if (tid == 0) {
#pragma unroll
        for (int i = 0; i < 3; i++) { mbar_inval(sb + 16 + i * 8); mbar_inval(sb + 48 + i * 8); }
        mbar_inval(sb + 80);
    }
    __syncthreads();
    if (wid == 0) tmem_dealloc(tmem, 512);
#endif
}

// ===================== tcgen05 GEMM2: 3-stage mbarrier pipeline ============
// stage (48KB): A0h A0l A1h A1l (8KB each) + Bh Bl (8KB each)
#define G2_STG 49152
#define G2_SMEM (1024 + 3*G2_STG)

#if TC_OK
__device__ __forceinline__ void g2_fill(uint32_t sb, int buf, int kc,
                                        int grp, int e, int nb0, int tid) {
    uint32_t st = sb + 1024 + buf * G2_STG;
#pragma unroll
    for (int i = 0; i < 8; i++) {           // A
        int id = i * 256 + tid;
        int reg = id >> 9, c2 = id & 511;
        int row = c2 >> 2, cb = c2 & 3;
        uint32_t off = SWZ64((uint32_t)(row * 64 + cb * 16));
        const bf16* srcA = (reg & 1) ? gUl : gUh;
        const bf16* g = srcA + ((size_t)(grp * 256 + (reg >> 1) * 128 + row) * HIDV + kc + cb * 8);
        cp16(st + reg * 8192 + off, g);
    }
#pragma unroll
    for (int i = 0; i < 4; i++) {           // B: 2 regions x 512 chunks
        int id = i * 256 + tid;
        int reg = id >> 9, c2 = id & 511;
        int row = c2 >> 2, cb = c2 & 3;
        uint32_t off = SWZ64((uint32_t)(row * 64 + cb * 16));
        const bf16* srcB = reg ? gW3l : gW3h;
        const bf16* g = srcB + ((size_t)e * DIMV + nb0 + row) * HIDV + kc + cb * 8;
        cp16(st + 32768 + reg * 8192 + off, g);
    }
}
#endif

__global__ __launch_bounds__(256) void gemm2_tc(float* __restrict__ out) {
#if TC_OK
    extern __shared__ char smem[];
    uint32_t sb = smem_u32(smem);
    int tid = threadIdx.x, wid = tid >> 5, lane = tid & 31;
    int grp = blockIdx.y, nb0 = blockIdx.x * 128;
    int e = gGrpE[grp];

    if (wid == 0) tmem_alloc(sb, 256);
    if (tid == 0) {
#pragma unroll
        for (int i = 0; i < 3; i++) {
            mbar_init(sb + 16 + i * 8, 256);
            mbar_init(sb + 48 + i * 8, 1);
        }
        mbar_init(sb + 80, 1);
    }
    __syncthreads();
    uint32_t tmem;
    asm volatile("ld.shared.b32 %0, [%1];" : "=r"(tmem) : "r"(sb));

    const int NS = HIDV / KC;  // 64
    for (int s = 0; s < NS; s++) {
        int b = s % 3;
        if (s >= 3) mbar_wait(sb + 48 + b * 8, ((s - 3) / 3) & 1);
        g2_fill(sb, b, s * KC, grp, e, nb0, tid);
        cp_arrive(sb + 16 + b * 8);
        if (wid == 0) {
            mbar_wait(sb + 16 + b * 8, (s / 3) & 1);
            fence_async_smem();
            if (elect1()) {
                uint32_t st = sb + 1024 + b * G2_STG;
                uint64_t dA[2][2];
                dA[0][0] = desc64(st);          dA[0][1] = desc64(st + 8192);
                dA[1][0] = desc64(st + 16384);  dA[1][1] = desc64(st + 24576);
                uint64_t bh = desc64(st + 32768), bl = desc64(st + 40960);
#pragma unroll
                for (int t = 0; t < 2; t++) {
                    uint32_t D = tmem + t * 128;
#pragma unroll
                    for (int k = 0; k < 2; k++) {
                        uint32_t en = (s == 0 && k == 0) ? 0u : 1u;
                        uint64_t k2 = (uint64_t)(k * 2);
                        mma_ss(D, dA[t][0] + k2, bh + k2, en);
                        mma_ss(D, dA[t][0] + k2, bl + k2, 1u);
                        mma_ss(D, dA[t][1] + k2, bh + k2, 1u);
                    }
                }
                mma_commit(sb + 48 + b * 8);
            }
        }
    }
    if (wid == 0) {
        if (elect1()) mma_commit(sb + 80);
    }
    mbar_wait(sb + 80, 0);
    tm_fence_after();

    {
        int t = wid >> 2;
        uint32_t T = tmem + t * 128;
        int grow = grp * 256 + t * 128 + (wid & 3) * 32 + lane;
        int tok = gRowTok[grow];
        float p = (tok >= 0) ? gP[tok] : 0.f;
        float* o = (tok >= 0) ? (out + (size_t)tok * DIMV + nb0) : nullptr;
#pragma unroll
        for (int pq = 0; pq < 4; pq++) {
            uint32_t r[32];
            ldtm32(r, T + pq * 32);
            tm_wait_ld();
            if (tok >= 0) {
#pragma unroll
                for (int j = 0; j < 32; j++)
                    o[pq * 32 + j] =
                        __bfloat162float(__float2bfloat16(__uint_as_float(r[j]))) * p;
            }
        }
    }
    __syncthreads();
    if (tid == 0) {
#pragma unroll
        for (int i = 0; i < 3; i++) { mbar_inval(sb + 16 + i * 8); mbar_inval(sb + 48 + i * 8); }
        mbar_inval(sb + 80);
    }
    __syncthreads();
    if (wid == 0) tmem_dealloc(tmem, 256);
#endif
}

// ===================== HMMA fallback path ==================================
#if !TC_OK && defined(__CUDA_ARCH__)
#define HM_OK 1
#else
#define HM_OK 0
#endif
#define HBN 64

#if HM_OK
__device__ __forceinline__ void h1_load(
    bf16* a_h, bf16* a_l, bf16* b1h, bf16* b1l, bf16* b2h, bf16* b2l,
    const bf16* gAh, const bf16* gAl,
    const bf16* gB1h, const bf16* gB1l, const bf16* gB2h, const bf16* gB2l,
    int kc, int tid)
{
#pragma unroll
    for (int i = 0; i < 2; i++) {
        int q = tid * 2 + i, r = q >> 2, ko = (q & 3) * 8;
        size_t go = (size_t)r * DIMV + kc + ko;
        cp16(smem_u32(a_h + r * SROW + ko), gAh + go);
        cp16(smem_u32(a_l + r * SROW + ko), gAl + go);
    }
    {
        int r = tid >> 2, ko = (tid & 3) * 8;
        size_t go = (size_t)r * DIMV + kc + ko;
        cp16(smem_u32(b1h + r * SROW + ko), gB1h + go);
        cp16(smem_u32(b1l + r * SROW + ko), gB1l + go);
        cp16(smem_u32(b2h + r * SROW + ko), gB2h + go);
        cp16(smem_u32(b2l + r * SROW + ko), gB2l + go);
    }
    cpcommit();
}
#endif

__global__ __launch_bounds__(256, 1) void gemm1_hm() {
#if HM_OK
    extern __shared__ bf16 smh[];
    bf16* Ah  = smh;
    bf16* Al  = Ah  + 2 * BM * SROW;
    bf16* B1h = Al  + 2 * BM * SROW;
    bf16* B1l = B1h + 2 * HBN * SROW;
    bf16* B2h = B1l + 2 * HBN * SROW;
    bf16* B2l = B2h + 2 * HBN * SROW;

    int tile = blockIdx.y, nb0 = blockIdx.x * HBN;
    int e = gGrpE[tile >> 1];
    int tid = threadIdx.x, lane = tid & 31, warp = tid >> 5;
    int wm = warp & 3, wn = warp >> 2;
    int g = lane >> 2, t4 = lane & 3;

    const bf16* gAh  = gXh + (size_t)tile * BM * DIMV;
    const bf16* gAl  = gXl + (size_t)tile * BM * DIMV;
    const bf16* gB1h = gW1h + ((size_t)e * HIDV + nb0) * DIMV;
    const bf16* gB1l = gW1l + ((size_t)e * HIDV + nb0) * DIMV;
    const bf16* gB2h = gW2h + ((size_t)e * HIDV + nb0) * DIMV;
    const bf16* gB2l = gW2l + ((size_t)e * HIDV + nb0) * DIMV;

    float acc1[2][4][4], acc2[2][4][4];
#pragma unroll
    for (int m = 0; m < 2; m++)
#pragma unroll
        for (int n = 0; n < 4; n++)
#pragma unroll
            for (int i = 0; i < 4; i++) { acc1[m][n][i] = 0.f; acc2[m][n][i] = 0.f; }

    const int NSTEP = DIMV / BK;
    h1_load(Ah, Al, B1h, B1l, B2h, B2l, gAh, gAl, gB1h, gB1l, gB2h, gB2l, 0, tid);

    for (int s = 0; s < NSTEP; s++) {
        if (s + 1 < NSTEP) {
            int buf = (s + 1) & 1;
            h1_load(Ah + buf * BM * SROW, Al + buf * BM * SROW,
                    B1h + buf * HBN * SROW, B1l + buf * HBN * SROW,
                    B2h + buf * HBN * SROW, B2l + buf * HBN * SROW,
                    gAh, gAl, gB1h, gB1l, gB2h, gB2l, (s + 1) * BK, tid);
            asm volatile("cp.async.wait_group 1;\n");
        } else {
            asm volatile("cp.async.wait_group 0;\n");
        }
        __syncthreads();
        int buf = s & 1;
        const bf16* a_h = Ah  + buf * BM * SROW;
        const bf16* a_l = Al  + buf * BM * SROW;
        const bf16* b1h = B1h + buf * HBN * SROW;
        const bf16* b1l = B1l + buf * HBN * SROW;
        const bf16* b2h = B2h + buf * HBN * SROW;
        const bf16* b2l = B2l + buf * HBN * SROW;

#pragma unroll
        for (int kk = 0; kk < 2; kk++) {
            int kb = kk * 16;
            unsigned Afh[2][4], Afl[2][4];
#pragma unroll
            for (int mt = 0; mt < 2; mt++) {
                int rb = wm * 32 + mt * 16 + g;
                const bf16* p = a_h + rb * SROW + kb + t4 * 2;
                Afh[mt][0] = *(const unsigned*)(p);
                Afh[mt][1] = *(const unsigned*)(p + 8 * SROW);
                Afh[mt][2] = *(const unsigned*)(p + 8);
                Afh[mt][3] = *(const unsigned*)(p + 8 * SROW + 8);
                const bf16* q = a_l + rb * SROW + kb + t4 * 2;
                Afl[mt][0] = *(const unsigned*)(q);
                Afl[mt][1] = *(const unsigned*)(q + 8 * SROW);
                Afl[mt][2] = *(const unsigned*)(q + 8);
                Afl[mt][3] = *(const unsigned*)(q + 8 * SROW + 8);
            }
            {
                unsigned Bh[4][2], Bl[4][2];
#pragma unroll
                for (int nt = 0; nt < 4; nt++) {
                    int nr = wn * 32 + nt * 8 + g;
                    const bf16* p = b1h + nr * SROW + kb + t4 * 2;
                    Bh[nt][0] = *(const unsigned*)(p);
                    Bh[nt][1] = *(const unsigned*)(p + 8);
                    const bf16* q = b1l + nr * SROW + kb + t4 * 2;
                    Bl[nt][0] = *(const unsigned*)(q);
                    Bl[nt][1] = *(const unsigned*)(q + 8);
                }
#pragma unroll
                for (int mt = 0; mt < 2; mt++)
#pragma unroll
                    for (int nt = 0; nt < 4; nt++) {
                        mma_bf16(acc1[mt][nt], Afh[mt], Bh[nt]);
                        mma_bf16(acc1[mt][nt], Afh[mt], Bl[nt]);
                        mma_bf16(acc1[mt][nt], Afl[mt], Bh[nt]);
                    }
            }
            {
                unsigned Bh[4][2], Bl[4][2];
#pragma unroll
                for (int nt = 0; nt < 4; nt++) {
                    int nr = wn * 32 + nt * 8 + g;
                    const bf16* p = b2h + nr * SROW + kb + t4 * 2;
                    Bh[nt][0] = *(const unsigned*)(p);
                    Bh[nt][1] = *(const unsigned*)(p + 8);
                    const bf16* q = b2l + nr * SROW + kb + t4 * 2;
                    Bl[nt][0] = *(const unsigned*)(q);
                    Bl[nt][1] = *(const unsigned*)(q + 8);
                }
#pragma unroll
                for (int mt = 0; mt < 2; mt++)
#pragma unroll
                    for (int nt = 0; nt < 4; nt++) {
                        mma_bf16(acc2[mt][nt], Afh[mt], Bh[nt]);
                        mma_bf16(acc2[mt][nt], Afh[mt], Bl[nt]);
                        mma_bf16(acc2[mt][nt], Afl[mt], Bh[nt]);
                    }
            }
        }
        __syncthreads();
    }

#pragma unroll
    for (int mt = 0; mt < 2; mt++) {
#pragma unroll
        for (int nt = 0; nt < 4; nt++) {
            int lr = wm * 32 + mt * 16 + g;
            int grow = tile * 128 + lr;
            int col = nb0 + wn * 32 + nt * 8 + t4 * 2;
            const float* c1 = acc1[mt][nt];
            const float* c2 = acc2[mt][nt];
#pragma unroll
            for (int half = 0; half < 2; half++) {
                int r = grow + half * 8;
                float h1a = c1[half * 2 + 0], h1b = c1[half * 2 + 1];
                float h2a = c2[half * 2 + 0], h2b = c2[half * 2 + 1];
                float ua = h1a * (1.f / (1.f + expf(-h1a))) * h2a;
                float ub = h1b * (1.f / (1.f + expf(-h1b))) * h2b;
                bf16 ha, la, hb, lb;
                split2(ua, ha, la);
                split2(ub, hb, lb);
                __nv_bfloat162 vh; vh.x = ha; vh.y = hb;
                __nv_bfloat162 vl; vl.x = la; vl.y = lb;
                *(__nv_bfloat162*)(gUh + (size_t)r * HIDV + col) = vh;
                *(__nv_bfloat162*)(gUl + (size_t)r * HIDV + col) = vl;
            }
        }
    }
#endif
}

#if HM_OK
__device__ __forceinline__ void h2_load(
    bf16* a_h, bf16* a_l, bf16* bh, bf16* bl,
    const bf16* gAh, const bf16* gAl, const bf16* gBh, const bf16* gBl,
    int kc, int tid)
{
#pragma unroll
    for (int i = 0; i < 2; i++) {
        int q = tid * 2 + i, r = q >> 2, ko = (q & 3) * 8;
        size_t go = (size_t)r * HIDV + kc + ko;
        cp16(smem_u32(a_h + r * SROW + ko), gAh + go);
        cp16(smem_u32(a_l + r * SROW + ko), gAl + go);
    }
    {
        int r = tid >> 2, ko = (tid & 3) * 8;
        size_t go = (size_t)r * HIDV + kc + ko;
        cp16(smem_u32(bh + r * SROW + ko), gBh + go);
        cp16(smem_u32(bl + r * SROW + ko), gBl + go);
    }
    cpcommit();
}
#endif

__global__ __launch_bounds__(256, 1) void gemm2_hm(float* __restrict__ out) {
#if HM_OK
    extern __shared__ bf16 smh[];
    bf16* Ah = smh;
    bf16* Al = Ah + 2 * BM * SROW;
    bf16* Bh = Al + 2 * BM * SROW;
    bf16* Bl = Bh + 2 * HBN * SROW;

    int tile = blockIdx.y, nb0 = blockIdx.x * HBN;
    int e = gGrpE[tile >> 1];
    int tid = threadIdx.x, lane = tid & 31, warp = tid >> 5;
    int wm = warp & 3, wn = warp >> 2;
    int g = lane >> 2, t4 = lane & 3;

    const bf16* gAh2 = gUh + (size_t)tile * BM * HIDV;
    const bf16* gAl2 = gUl + (size_t)tile * BM * HIDV;
    const bf16* gBh2 = gW3h + ((size_t)e * DIMV + nb0) * HIDV;
    const bf16* gBl2 = gW3l + ((size_t)e * DIMV + nb0) * HIDV;

    float acc[2][4][4];
#pragma unroll
    for (int m = 0; m < 2; m++)
#pragma unroll
        for (int n = 0; n < 4; n++)
#pragma unroll
            for (int i = 0; i < 4; i++) acc[m][n][i] = 0.f;

    const int NSTEP = HIDV / BK;
    h2_load(Ah, Al, Bh, Bl, gAh2, gAl2, gBh2, gBl2, 0, tid);

    for (int s = 0; s < NSTEP; s++) {
        if (s + 1 < NSTEP) {
            int buf = (s + 1) & 1;
            h2_load(Ah + buf * BM * SROW, Al + buf * BM * SROW,
                    Bh + buf * HBN * SROW, Bl + buf * HBN * SROW,
                    gAh2, gAl2, gBh2, gBl2, (s + 1) * BK, tid);
            asm volatile("cp.async.wait_group 1;\n");
        } else {
            asm volatile("cp.async.wait_group 0;\n");
        }
        __syncthreads();
        int buf = s & 1;
        const bf16* a_h = Ah + buf * BM * SROW;
        const bf16* a_l = Al + buf * BM * SROW;
        const bf16* b_h = Bh + buf * HBN * SROW;
        const bf16* b_l = Bl + buf * HBN * SROW;

#pragma unroll
        for (int kk = 0; kk < 2; kk++) {
            int kb = kk * 16;
            unsigned Afh[2][4], Afl[2][4];
#pragma unroll
            for (int mt = 0; mt < 2; mt++) {
                int rb = wm * 32 + mt * 16 + g;
                const bf16* p = a_h + rb * SROW + kb + t4 * 2;
                Afh[mt][0] = *(const unsigned*)(p);
                Afh[mt][1] = *(const unsigned*)(p + 8 * SROW);
                Afh[mt][2] = *(const unsigned*)(p + 8);
                Afh[mt][3] = *(const unsigned*)(p + 8 * SROW + 8);
                const bf16* q = a_l + rb * SROW + kb + t4 * 2;
                Afl[mt][0] = *(const unsigned*)(q);
                Afl[mt][1] = *(const unsigned*)(q + 8 * SROW);
                Afl[mt][2] = *(const unsigned*)(q + 8);
                Afl[mt][3] = *(const unsigned*)(q + 8 * SROW + 8);
            }
            unsigned Bfh[4][2], Bfl[4][2];
#pragma unroll
            for (int nt = 0; nt < 4; nt++) {
                int nr = wn * 32 + nt * 8 + g;
                const bf16* p = b_h + nr * SROW + kb + t4 * 2;
                Bfh[nt][0] = *(const unsigned*)(p);
                Bfh[nt][1] = *(const unsigned*)(p + 8);
                const bf16* q = b_l + nr * SROW + kb + t4 * 2;
                Bfl[nt][0] = *(const unsigned*)(q);
                Bfl[nt][1] = *(const unsigned*)(q + 8);
            }
#pragma unroll
            for (int mt = 0; mt < 2; mt++)
#pragma unroll
                for (int nt = 0; nt < 4; nt++) {
                    mma_bf16(acc[mt][nt], Afh[mt], Bfh[nt]);
                    mma_bf16(acc[mt][nt], Afh[mt], Bfl[nt]);
                    mma_bf16(acc[mt][nt], Afl[mt], Bfh[nt]);
                }
        }
        __syncthreads();
    }

#pragma unroll
    for (int mt = 0; mt < 2; mt++) {
        int lr = wm * 32 + mt * 16 + g;
        int grow = tile * 128 + lr;
        int tokA = gRowTok[grow];
        int tokB = gRowTok[grow + 8];
        float pA = (tokA >= 0) ? gP[tokA] : 0.f;
        float pB = (tokB >= 0) ? gP[tokB] : 0.f;
#pragma unroll
        for (int nt = 0; nt < 4; nt++) {
            int col = nb0 + wn * 32 + nt * 8 + t4 * 2;
            const float* c = acc[mt][nt];
            if (tokA >= 0) {
                out[(size_t)tokA * DIMV + col]     = __bfloat162float(__float2bfloat16(c[0])) * pA;
                out[(size_t)tokA * DIMV + col + 1] = __bfloat162float(__float2bfloat16(c[1])) * pA;
            }
            if (tokB >= 0) {
                out[(size_t)tokB * DIMV + col]     = __bfloat162float(__float2bfloat16(c[2])) * pB;
                out[(size_t)tokB * DIMV + col + 1] = __bfloat162float(__float2bfloat16(c[3])) * pB;
            }
        }
    }
#endif
}

// ------------------------- launcher ----------------------------------------
extern "C" void kernel_launch(void* const* d_in, const int* in_sizes, int n_in,
                              void* d_out, int out_size) {
    const float* x  = (const float*)d_in[0];
    const float* rw = (const float*)d_in[1];
    const float* rb = (const float*)d_in[2];
    const float* w1 = (const float*)d_in[3];
    const float* w2 = (const float*)d_in[4];
    const float* w3 = (const float*)d_in[5];
    float* out = (float*)d_out;

    const int SH1 = (int)((2 * BM * SROW * 2 + 2 * HBN * SROW * 4) * sizeof(bf16));
    const int SH2 = (int)((2 * BM * SROW * 2 + 2 * HBN * SROW * 2) * sizeof(bf16));
    cudaFuncSetAttribute(gemm1_tc, cudaFuncAttributeMaxDynamicSharedMemorySize, G1_SMEM);
    cudaFuncSetAttribute(gemm2_tc, cudaFuncAttributeMaxDynamicSharedMemorySize, G2_SMEM);
    cudaFuncSetAttribute(gemm1_hm, cudaFuncAttributeMaxDynamicSharedMemorySize, SH1);
    cudaFuncSetAttribute(gemm2_hm, cudaFuncAttributeMaxDynamicSharedMemorySize, SH2);

    // order chosen so gemm1_tc is launch index 5 (ncu -s 5 -c 1 slot)
    router_k<<<TOKV / 8, 256>>>(x, rw, rb);                          // 0
    plan_k<<<1, 512>>>();                                            // 1
    gather_k<<<MAXROWS, 256>>>(x);                                   // 2
    tsplit_k<<<dim3(HIDV / 64, DIMV / 64, NEXP), 256>>>(w1, DIMV, HIDV, 0); // 3
    tsplit_k<<<dim3(HIDV / 64, DIMV / 64, NEXP), 256>>>(w2, DIMV, HIDV, 1); // 4
    gemm1_tc<<<dim3(HIDV / 128, MAXGRP), 256, G1_SMEM>>>();          // 5
    gemm1_hm<<<dim3(HIDV / HBN, NTILE), 256, SH1>>>();               // 6
    tsplit_k<<<dim3(DIMV / 64, HIDV / 64, NEXP), 256>>>(w3, HIDV, DIMV, 2); // 7
    gemm2_tc<<<dim3(DIMV / 128, MAXGRP), 256, G2_SMEM>>>(out);       // 8
    gemm2_hm<<<dim3(DIMV / HBN, NTILE), 256, SH2>>>(out);            // 9
}

// round 8
// speedup vs baseline: 1.2823x; 1.2823x over previous
#include <cuda_runtime.h>
#include <cuda_bf16.h>
#include <cstdint>

typedef __nv_bfloat16 bf16;

// tcgen05 is only legal in an arch-specific (compute_103a) device pass.
#if defined(__CUDA_ARCH__) && (__CUDA_ARCH__ == 1030) && \
    (defined(__CUDA_ARCH_FEAT_SM103_ALL) || defined(__CUDA_ARCH_FEAT_SM100_ALL))
#define TC_OK 1
#else
#define TC_OK 0
#endif

#define DIMV 768
#define HIDV 2048
#define TOKV 4096
#define NEXP 8
#define MAXGRP 24            // 256-row expert groups
#define NTILE (MAXGRP*2)     // 128-row tiles (HM path)
#define MAXROWS (MAXGRP*256) // 6144

#define BM 128
#define KC 32           // tcgen05 stage K elems (64B rows, SW64)
#define BK 32           // HMMA stage K elems
#define SROW 40         // HMMA smem row pitch (bf16)

// ------------------------- device scratch ---------------------------------
__device__ bf16 gW1h[(size_t)NEXP*HIDV*DIMV];
__device__ bf16 gW1l[(size_t)NEXP*HIDV*DIMV];
__device__ bf16 gW2h[(size_t)NEXP*HIDV*DIMV];
__device__ bf16 gW2l[(size_t)NEXP*HIDV*DIMV];
__device__ bf16 gW3h[(size_t)NEXP*DIMV*HIDV];
__device__ bf16 gW3l[(size_t)NEXP*DIMV*HIDV];
__device__ bf16 gXh[(size_t)MAXROWS*DIMV];
__device__ bf16 gXl[(size_t)MAXROWS*DIMV];
__device__ bf16 gUh[(size_t)MAXROWS*HIDV];
__device__ bf16 gUl[(size_t)MAXROWS*HIDV];
__device__ int   gTokE[TOKV];
__device__ float gP[TOKV];
__device__ int   gRowTok[MAXROWS];
__device__ int   gGrpE[MAXGRP];

// ------------------------- common helpers ----------------------------------
__device__ __forceinline__ uint32_t smem_u32(const void* p) {
    uint32_t a;
    asm("{ .reg .u64 t; cvta.to.shared.u64 t, %1; cvt.u32.u64 %0, t; }" : "=r"(a) : "l"(p));
    return a;
}
__device__ __forceinline__ void cp16(uint32_t s, const void* g) {
    asm volatile("cp.async.cg.shared.global [%0], [%1], 16;\n" :: "r"(s), "l"(g));
}
__device__ __forceinline__ void cpcommit() { asm volatile("cp.async.commit_group;\n"); }
__device__ __forceinline__ void split2(float v, bf16& h, bf16& l) {
    h = __float2bfloat16(v);
    l = __float2bfloat16(v - __bfloat162float(h));
}
__device__ __forceinline__ void mma_bf16(float* c, const unsigned* a, const unsigned* b) {
    asm volatile(
        "mma.sync.aligned.m16n8k16.row.col.f32.bf16.bf16.f32 "
        "{%0,%1,%2,%3},{%4,%5,%6,%7},{%8,%9},{%0,%1,%2,%3};\n"
        : "+f"(c[0]), "+f"(c[1]), "+f"(c[2]), "+f"(c[3])
        : "r"(a[0]), "r"(a[1]), "r"(a[2]), "r"(a[3]), "r"(b[0]), "r"(b[1]));
}

#define SWZ64(x) ((x) ^ (((x) >> 3) & 0x30))

// ------------------------- tcgen05 helpers (bodies arch-gated) -------------
__device__ __forceinline__ uint32_t elect1() {
    uint32_t p = 0;
#if TC_OK
    asm volatile("{ .reg .pred p; elect.sync _|p, 0xFFFFFFFF; selp.b32 %0,1,0,p; }" : "=r"(p));
#endif
    return p;
}
__device__ __forceinline__ uint64_t desc64(uint32_t addr) {
    // SW64 layout: layout_type=4, version=1 (Blackwell), SBO=32 (512B), LBO=1 (16B)
    const uint64_t base = (uint64_t(4) << 61) | (uint64_t(1) << 46)
                        | (uint64_t(32) << 32) | (uint64_t(1) << 16);
    return base | ((uint64_t)(addr >> 4) & 0x3FFF);
}
// kind::f16 idesc: dtype=F32(1<<4), atype=BF16(1<<7), btype=BF16(1<<10),
// N/8<<17, M/16<<24.  M=128, N=128 -> 0x8200490
#define IDESC 0x8200490u

__device__ __forceinline__ void mma_ss(uint32_t d, uint64_t ad, uint64_t bd, uint32_t en) {
#if TC_OK
    asm volatile(
        "{\n .reg .pred p;\n setp.ne.u32 p, %4, 0;\n"
        " tcgen05.mma.cta_group::1.kind::f16 [%0], %1, %2, %3, {%5,%5,%5,%5}, p;\n}"
        :: "r"(d), "l"(ad), "l"(bd), "r"(IDESC), "r"(en), "r"(0u) : "memory");
#endif
}
__device__ __forceinline__ void mma_commit(uint32_t mbar) {
#if TC_OK
    asm volatile(
        "tcgen05.commit.cta_group::1.mbarrier::arrive::one.shared::cluster.b64 [%0];"
        :: "r"(mbar) : "memory");
#endif
}
__device__ __forceinline__ void mbar_init(uint32_t a, uint32_t c) {
#if TC_OK
    asm volatile("mbarrier.init.shared.b64 [%0], %1;" :: "r"(a), "r"(c) : "memory");
#endif
}
__device__ __forceinline__ void mbar_inval(uint32_t a) {
#if TC_OK
    asm volatile("mbarrier.inval.shared.b64 [%0];" :: "r"(a) : "memory");
#endif
}
__device__ __forceinline__ void mbar_wait(uint32_t a, uint32_t ph) {
#if TC_OK
    uint32_t ok = 0;
    while (!ok) {
        asm volatile(
            "{\n .reg .pred P;\n"
            " mbarrier.try_wait.parity.acquire.cta.shared::cta.b64 P, [%1], %2, 0x989680;\n"
            " selp.b32 %0, 1, 0, P;\n}"
            : "=r"(ok) : "r"(a), "r"(ph) : "memory");
    }
#endif
}
__device__ __forceinline__ void tmem_alloc(uint32_t smem_ptr, uint32_t ncols) {
#if TC_OK
    asm volatile("tcgen05.alloc.cta_group::1.sync.aligned.shared::cta.b32 [%0], %1;"
                 :: "r"(smem_ptr), "r"(ncols) : "memory");
#endif
}
__device__ __forceinline__ void tmem_dealloc(uint32_t tmem, uint32_t ncols) {
#if TC_OK
    asm volatile("tcgen05.relinquish_alloc_permit.cta_group::1.sync.aligned;");
    asm volatile("tcgen05.dealloc.cta_group::1.sync.aligned.b32 %0, %1;" :: "r"(tmem), "r"(ncols));
#endif
}
__device__ __forceinline__ void ldtm32(uint32_t* r, uint32_t ta) {
#if TC_OK
    asm volatile(
        "tcgen05.ld.sync.aligned.32x32b.x32.b32 "
        "{%0,%1,%2,%3,%4,%5,%6,%7,%8,%9,%10,%11,%12,%13,%14,%15,"
        "%16,%17,%18,%19,%20,%21,%22,%23,%24,%25,%26,%27,%28,%29,%30,%31}, [%32];"
        : "=r"(r[0]), "=r"(r[1]), "=r"(r[2]), "=r"(r[3]), "=r"(r[4]), "=r"(r[5]),
          "=r"(r[6]), "=r"(r[7]), "=r"(r[8]), "=r"(r[9]), "=r"(r[10]), "=r"(r[11]),
          "=r"(r[12]), "=r"(r[13]), "=r"(r[14]), "=r"(r[15]), "=r"(r[16]), "=r"(r[17]),
          "=r"(r[18]), "=r"(r[19]), "=r"(r[20]), "=r"(r[21]), "=r"(r[22]), "=r"(r[23]),
          "=r"(r[24]), "=r"(r[25]), "=r"(r[26]), "=r"(r[27]), "=r"(r[28]), "=r"(r[29]),
          "=r"(r[30]), "=r"(r[31])
        : "r"(ta));
#endif
}
__device__ __forceinline__ void tm_wait_ld() {
#if TC_OK
    asm volatile("tcgen05.wait::ld.sync.aligned;" ::: "memory");
#endif
}
__device__ __forceinline__ void tm_fence_after() {
#if TC_OK
    asm volatile("tcgen05.fence::after_thread_sync;" ::: "memory");
#endif
}
__device__ __forceinline__ void fence_async_smem() {
#if TC_OK
    asm volatile("fence.proxy.async.shared::cta;" ::: "memory");
#endif
}

// ------------------------- router ------------------------------------------
__global__ void router_k(const float* __restrict__ x,
                         const float* __restrict__ rw,
                         const float* __restrict__ rb) {
    int wid  = (blockIdx.x * blockDim.x + threadIdx.x) >> 5;
    int lane = threadIdx.x & 31;
    if (wid >= TOKV) return;
    const float* xr = x + (size_t)wid * DIMV;
    float acc[NEXP];
#pragma unroll
    for (int e = 0; e < NEXP; e++) acc[e] = 0.f;
    for (int k = lane; k < DIMV; k += 32) {
        float xv = xr[k];
        const float* w = rw + k * NEXP;
#pragma unroll
        for (int e = 0; e < NEXP; e++) acc[e] += xv * w[e];
    }
#pragma unroll
    for (int off = 16; off; off >>= 1)
#pragma unroll
        for (int e = 0; e < NEXP; e++)
            acc[e] += __shfl_xor_sync(0xffffffffu, acc[e], off);
    if (lane == 0) {
        float l[NEXP];
        float m = -1e30f; int mi = 0;
#pragma unroll
        for (int e = 0; e < NEXP; e++) {
            l[e] = acc[e] + rb[e];
            if (l[e] > m) { m = l[e]; mi = e; }
        }
        float s = 0.f;
#pragma unroll
        for (int e = 0; e < NEXP; e++) s += expf(l[e] - m);
        gTokE[wid] = mi;
        gP[wid] = 1.f / s;
    }
}

// ------------------------- plan: 256-row expert groups ----------------------
__global__ void plan_k() {
    __shared__ int cnt[NEXP], cur[NEXP], base[NEXP];
    int tid = threadIdx.x;
    if (tid < NEXP) { cnt[tid] = 0; cur[tid] = 0; }
    __syncthreads();
    for (int t = tid; t < TOKV; t += blockDim.x) atomicAdd(&cnt[gTokE[t]], 1);
    __syncthreads();
    if (tid == 0) {
        int acc = 0, gc = 0;
        for (int e = 0; e < NEXP; e++) {
            base[e] = acc;
            int ng = (cnt[e] + 255) >> 8;
            for (int i = 0; i < ng && gc < MAXGRP; i++) gGrpE[gc++] = e;
            acc += ng * 256;
        }
        for (; gc < MAXGRP; gc++) gGrpE[gc] = 0;
    }
    __syncthreads();
    for (int r = tid; r < MAXROWS; r += blockDim.x) gRowTok[r] = -1;
    __syncthreads();
    for (int t = tid; t < TOKV; t += blockDim.x) {
        int e = gTokE[t];
        int s = atomicAdd(&cur[e], 1);
        gRowTok[base[e] + s] = t;
    }
}

// ---------------- weight transpose + bf16 split (coalesced) ----------------
// src [E][R][C] f32 -> dst hi/lo [E][C][R] bf16
// tsplit12: both W1 and W2 in one launch (z in 0..15: z<8 -> W1[e=z], else W2)
__global__ void tsplit12_k(const float* __restrict__ w1, const float* __restrict__ w2) {
    __shared__ float tile[64][65];
    int z = blockIdx.z;
    int e = z & 7;
    const float* src = (z < 8) ? w1 : w2;
    bf16* dh = (z < 8) ? gW1h : gW2h;
    bf16* dl = (z < 8) ? gW1l : gW2l;
    const int R = DIMV, C = HIDV;
    int c0 = blockIdx.x * 64, r0 = blockIdx.y * 64;
    int tid = threadIdx.x;
    const float* s = src + (size_t)e * R * C;
#pragma unroll
    for (int i = 0; i < 16; i++) {
        int idx = i * 256 + tid;
        int r = idx >> 6, c = idx & 63;
        tile[r][c] = s[(size_t)(r0 + r) * C + c0 + c];
    }
    __syncthreads();
    bf16* dhp = dh + (size_t)e * C * R;
    bf16* dlp = dl + (size_t)e * C * R;
#pragma unroll
    for (int i = 0; i < 8; i++) {
        int idx = i * 256 + tid;
        int c = idx >> 5, rp = idx & 31, r = rp * 2;
        float v0 = tile[r][c], v1 = tile[r + 1][c];
        bf16 h0, l0, h1, l1;
        split2(v0, h0, l0);
        split2(v1, h1, l1);
        __nv_bfloat162 vh; vh.x = h0; vh.y = h1;
        __nv_bfloat162 vl; vl.x = l0; vl.y = l1;
        size_t o = (size_t)(c0 + c) * R + r0 + r;
        *(__nv_bfloat162*)(dhp + o) = vh;
        *(__nv_bfloat162*)(dlp + o) = vl;
    }
}

__global__ void tsplit3_k(const float* __restrict__ src) {
    __shared__ float tile[64][65];
    const int R = HIDV, C = DIMV;
    int e = blockIdx.z;
    int c0 = blockIdx.x * 64, r0 = blockIdx.y * 64;
    int tid = threadIdx.x;
    const float* s = src + (size_t)e * R * C;
#pragma unroll
    for (int i = 0; i < 16; i++) {
        int idx = i * 256 + tid;
        int r = idx >> 6, c = idx & 63;
        tile[r][c] = s[(size_t)(r0 + r) * C + c0 + c];
    }
    __syncthreads();
    bf16* dhp = gW3h + (size_t)e * C * R;
    bf16* dlp = gW3l + (size_t)e * C * R;
#pragma unroll
    for (int i = 0; i < 8; i++) {
        int idx = i * 256 + tid;
        int c = idx >> 5, rp = idx & 31, r = rp * 2;
        float v0 = tile[r][c], v1 = tile[r + 1][c];
        bf16 h0, l0, h1, l1;
        split2(v0, h0, l0);
        split2(v1, h1, l1);
        __nv_bfloat162 vh; vh.x = h0; vh.y = h1;
        __nv_bfloat162 vl; vl.x = l0; vl.y = l1;
        size_t o = (size_t)(c0 + c) * R + r0 + r;
        *(__nv_bfloat162*)(dhp + o) = vh;
        *(__nv_bfloat162*)(dlp + o) = vl;
    }
}

// ------------------------- gather X + split --------------------------------
__global__ void gather_k(const float* __restrict__ x) {
    int row = blockIdx.x;
    int tok = gRowTok[row];
    for (int k = threadIdx.x; k < DIMV; k += blockDim.x) {
        float v = (tok >= 0) ? x[(size_t)tok * DIMV + k] : 0.f;
        bf16 h, l; split2(v, h, l);
        gXh[(size_t)row * DIMV + k] = h;
        gXl[(size_t)row * DIMV + k] = l;
    }
}

// ===================== tcgen05 GEMM1: 3-buffer overlap pipeline ============
// smem: [0] tmem ptr, [16..40) empty[3] mbarriers
// stage (64KB): A0h A0l A1h A1l B1h B1l B2h B2l, 8KB each
#define G1_STG 65536
#define G1_SMEM (1024 + 3*G1_STG)

#if TC_OK
__device__ __forceinline__ void g1_fill(uint32_t sb, int buf, int kc,
                                        int grp, int e, int nb0, int tid) {
    uint32_t st = sb + 1024 + buf * G1_STG;
#pragma unroll
    for (int i = 0; i < 8; i++) {           // A: 4 regions x 512 chunks
        int id = i * 256 + tid;
        int reg = id >> 9, c2 = id & 511;
        int row = c2 >> 2, cb = c2 & 3;
        uint32_t off = SWZ64((uint32_t)(row * 64 + cb * 16));
        const bf16* srcA = (reg & 1) ? gXl : gXh;
        const bf16* g = srcA + ((size_t)(grp * 256 + (reg >> 1) * 128 + row) * DIMV + kc + cb * 8);
        cp16(st + reg * 8192 + off, g);
    }
#pragma unroll
    for (int i = 0; i < 8; i++) {           // B: 4 regions x 512 chunks
        int id = i * 256 + tid;
        int reg = id >> 9, c2 = id & 511;
        int row = c2 >> 2, cb = c2 & 3;
        uint32_t off = SWZ64((uint32_t)(row * 64 + cb * 16));
        const bf16* srcB = (reg == 0) ? gW1h : (reg == 1) ? gW1l : (reg == 2) ? gW2h : gW2l;
        const bf16* g = srcB + ((size_t)e * HIDV + nb0 + row) * DIMV + kc + cb * 8;
        cp16(st + 32768 + reg * 8192 + off, g);
    }
    cpcommit();
}
#endif

__global__ __launch_bounds__(256) void gemm1_tc() {
#if TC_OK
    extern __shared__ char smem[];
    uint32_t sb = smem_u32(smem);
    int tid = threadIdx.x, wid = tid >> 5, lane = tid & 31;
    int grp = blockIdx.y, nb0 = blockIdx.x * 128;
    int e = gGrpE[grp];

    if (wid == 0) tmem_alloc(sb, 512);
    if (tid == 0) {
#pragma unroll
        for (int i = 0; i < 3; i++) mbar_init(sb + 16 + i * 8, 1);  // empty[i]
    }
    __syncthreads();
    uint32_t tmem;
    asm volatile("ld.shared.b32 %0, [%1];" : "=r"(tmem) : "r"(sb));

    const int NS = DIMV / KC;  // 24
    g1_fill(sb, 0, 0, grp, e, nb0, tid);
    g1_fill(sb, 1, KC, grp, e, nb0, tid);

    for (int s = 0; s < NS; s++) {
        if (s == NS - 1) asm volatile("cp.async.wait_group 0;\n");
        else             asm volatile("cp.async.wait_group 1;\n");
        __syncthreads();
        if (wid == 0) {
            fence_async_smem();
            if (elect1()) {
                int b = s % 3;
                uint32_t st = sb + 1024 + b * G1_STG;
                uint64_t dA[2][2];
                dA[0][0] = desc64(st);          dA[0][1] = desc64(st + 8192);
                dA[1][0] = desc64(st + 16384);  dA[1][1] = desc64(st + 24576);
                uint64_t b1h = desc64(st + 32768), b1l = desc64(st + 40960);
                uint64_t b2h = desc64(st + 49152), b2l = desc64(st + 57344);
#pragma unroll
                for (int t = 0; t < 2; t++) {
                    uint32_t D1 = tmem + t * 256, D2 = tmem + t * 256 + 128;
#pragma unroll
                    for (int k = 0; k < 2; k++) {
                        uint32_t en = (s == 0 && k == 0) ? 0u : 1u;
                        uint64_t k2 = (uint64_t)(k * 2);
                        mma_ss(D1, dA[t][0] + k2, b1h + k2, en);
                        mma_ss(D1, dA[t][0] + k2, b1l + k2, 1u);
                        mma_ss(D1, dA[t][1] + k2, b1h + k2, 1u);
                        mma_ss(D2, dA[t][0] + k2, b2h + k2, en);
                        mma_ss(D2, dA[t][0] + k2, b2l + k2, 1u);
                        mma_ss(D2, dA[t][1] + k2, b2h + k2, 1u);
                    }
                }
                mma_commit(sb + 16 + (s % 3) * 8);
            }
        }
        if (s + 2 < NS) {
            int b2 = (s + 2) % 3;
            if (s >= 1) mbar_wait(sb + 16 + b2 * 8, (uint32_t)(((s - 1) / 3) & 1));
            g1_fill(sb, b2, (s + 2) * KC, grp, e, nb0, tid);
        }
    }

    mbar_wait(sb + 16 + ((NS - 1) % 3) * 8, (uint32_t)(((NS - 1) / 3) & 1));
    tm_fence_after();

    {
        int t = wid >> 2;
        uint32_t T = tmem + t * 256;
        int grow = grp * 256 + t * 128 + (wid & 3) * 32 + lane;
        bf16* dh = gUh + (size_t)grow * HIDV + nb0;
        bf16* dl = gUl + (size_t)grow * HIDV + nb0;
#pragma unroll
        for (int p = 0; p < 4; p++) {
            uint32_t r1[32], r2[32];
            ldtm32(r1, T + p * 32);
            ldtm32(r2, T + 128 + p * 32);
            tm_wait_ld();
#pragma unroll
            for (int j = 0; j < 32; j += 2) {
                float h1a = __uint_as_float(r1[j]),     h2a = __uint_as_float(r2[j]);
                float h1b = __uint_as_float(r1[j + 1]), h2b = __uint_as_float(r2[j + 1]);
                float ua = h1a * (1.f / (1.f + expf(-h1a))) * h2a;
                float ub = h1b * (1.f / (1.f + expf(-h1b))) * h2b;
                bf16 ha, la, hb, lb;
                split2(ua, ha, la);
                split2(ub, hb, lb);
                __nv_bfloat162 vh; vh.x = ha; vh.y = hb;
                __nv_bfloat162 vl; vl.x = la; vl.y = lb;
                *(__nv_bfloat162*)(dh + p * 32 + j) = vh;
                *(__nv_bfloat162*)(dl + p * 32 + j) = vl;
            }
        }
    }
    __syncthreads();
    if (tid == 0) {
#pragma unroll
        for (int i = 0; i < 3; i++) mbar_inval(sb + 16 + i * 8);
    }
    __syncthreads();
    if (wid == 0) tmem_dealloc(tmem, 512);
#endif
}

// ===================== tcgen05 GEMM2: 3-buffer overlap pipeline ============
// stage (48KB): A0h A0l A1h A1l (8KB each) + Bh Bl (8KB each)
#define G2_STG 49152
#define G2_SMEM (1024 + 3*G2_STG)

#if TC_OK
__device__ __forceinline__ void g2_fill(uint32_t sb, int buf, int kc,
                                        int grp, int e, int nb0, int tid) {
    uint32_t st = sb + 1024 + buf * G2_STG;
#pragma unroll
    for (int i = 0; i < 8; i++) {           // A
        int id = i * 256 + tid;
        int reg = id >> 9, c2 = id & 511;
        int row = c2 >> 2, cb = c2 & 3;
        uint32_t off = SWZ64((uint32_t)(row * 64 + cb * 16));
        const bf16* srcA = (reg & 1) ? gUl : gUh;
        const bf16* g = srcA + ((size_t)(grp * 256 + (reg >> 1) * 128 + row) * HIDV + kc + cb * 8);
        cp16(st + reg * 8192 + off, g);
    }
#pragma unroll
    for (int i = 0; i < 4; i++) {           // B: 2 regions x 512 chunks
        int id = i * 256 + tid;
        int reg = id >> 9, c2 = id & 511;
        int row = c2 >> 2, cb = c2 & 3;
        uint32_t off = SWZ64((uint32_t)(row * 64 + cb * 16));
        const bf16* srcB = reg ? gW3l : gW3h;
        const bf16* g = srcB + ((size_t)e * DIMV + nb0 + row) * HIDV + kc + cb * 8;
        cp16(st + 32768 + reg * 8192 + off, g);
    }
    cpcommit();
}
#endif

__global__ __launch_bounds__(256) void gemm2_tc(float* __restrict__ out) {
#if TC_OK
    extern __shared__ char smem[];
    uint32_t sb = smem_u32(smem);
    int tid = threadIdx.x, wid = tid >> 5, lane = tid & 31;
    int grp = blockIdx.y, nb0 = blockIdx.x * 128;
    int e = gGrpE[grp];

    if (wid == 0) tmem_alloc(sb, 256);
    if (tid == 0) {
#pragma unroll
        for (int i = 0; i < 3; i++) mbar_init(sb + 16 + i * 8, 1);
    }
    __syncthreads();
    uint32_t tmem;
    asm volatile("ld.shared.b32 %0, [%1];" : "=r"(tmem) : "r"(sb));

    const int NS = HIDV / KC;  // 64
    g2_fill(sb, 0, 0, grp, e, nb0, tid);
    g2_fill(sb, 1, KC, grp, e, nb0, tid);

    for (int s = 0; s < NS; s++) {
        if (s == NS - 1) asm volatile("cp.async.wait_group 0;\n");
        else             asm volatile("cp.async.wait_group 1;\n");
        __syncthreads();
        if (wid == 0) {
            fence_async_smem();
            if (elect1()) {
                int b = s % 3;
                uint32_t st = sb + 1024 + b * G2_STG;
                uint64_t dA[2][2];
                dA[0][0] = desc64(st);          dA[0][1] = desc64(st + 8192);
                dA[1][0] = desc64(st + 16384);  dA[1][1] = desc64(st + 24576);
                uint64_t bh = desc64(st + 32768), bl = desc64(st + 40960);
#pragma unroll
                for (int t = 0; t < 2; t++) {
                    uint32_t D = tmem + t * 128;
#pragma unroll
                    for (int k = 0; k < 2; k++) {
                        uint32_t en = (s == 0 && k == 0) ? 0u : 1u;
                        uint64_t k2 = (uint64_t)(k * 2);
                        mma_ss(D, dA[t][0] + k2, bh + k2, en);
                        mma_ss(D, dA[t][0] + k2, bl + k2, 1u);
                        mma_ss(D, dA[t][1] + k2, bh + k2, 1u);
                    }
                }
                mma_commit(sb + 16 + (s % 3) * 8);
            }
        }
        if (s + 2 < NS) {
            int b2 = (s + 2) % 3;
            if (s >= 1) mbar_wait(sb + 16 + b2 * 8, (uint32_t)(((s - 1) / 3) & 1));
            g2_fill(sb, b2, (s + 2) * KC, grp, e, nb0, tid);
        }
    }

    mbar_wait(sb + 16 + ((NS - 1) % 3) * 8, (uint32_t)(((NS - 1) / 3) & 1));
    tm_fence_after();

    {
        int t = wid >> 2;
        uint32_t T = tmem + t * 128;
        int grow = grp * 256 + t * 128 + (wid & 3) * 32 + lane;
        int tok = gRowTok[grow];
        float p = (tok >= 0) ? gP[tok] : 0.f;
        float* o = (tok >= 0) ? (out + (size_t)tok * DIMV + nb0) : nullptr;
#pragma unroll
        for (int pq = 0; pq < 4; pq++) {
            uint32_t r[32];
            ldtm32(r, T + pq * 32);
            tm_wait_ld();
            if (tok >= 0) {
#pragma unroll
                for (int j = 0; j < 32; j++)
                    o[pq * 32 + j] =
                        __bfloat162float(__float2bfloat16(__uint_as_float(r[j]))) * p;
            }
        }
    }
    __syncthreads();
    if (tid == 0) {
#pragma unroll
        for (int i = 0; i < 3; i++) mbar_inval(sb + 16 + i * 8);
    }
    __syncthreads();
    if (wid == 0) tmem_dealloc(tmem, 256);
#endif
}

// ===================== HMMA fallback path ==================================
#if !TC_OK && defined(__CUDA_ARCH__)
#define HM_OK 1
#else
#define HM_OK 0
#endif
#define HBN 64

#if HM_OK
__device__ __forceinline__ void h1_load(
    bf16* a_h, bf16* a_l, bf16* b1h, bf16* b1l, bf16* b2h, bf16* b2l,
    const bf16* gAh, const bf16* gAl,
    const bf16* gB1h, const bf16* gB1l, const bf16* gB2h, const bf16* gB2l,
    int kc, int tid)
{
#pragma unroll
    for (int i = 0; i < 2; i++) {
        int q = tid * 2 + i, r = q >> 2, ko = (q & 3) * 8;
        size_t go = (size_t)r * DIMV + kc + ko;
        cp16(smem_u32(a_h + r * SROW + ko), gAh + go);
        cp16(smem_u32(a_l + r * SROW + ko), gAl + go);
    }
    {
        int r = tid >> 2, ko = (tid & 3) * 8;
        size_t go = (size_t)r * DIMV + kc + ko;
        cp16(smem_u32(b1h + r * SROW + ko), gB1h + go);
        cp16(smem_u32(b1l + r * SROW + ko), gB1l + go);
        cp16(smem_u32(b2h + r * SROW + ko), gB2h + go);
        cp16(smem_u32(b2l + r * SROW + ko), gB2l + go);
    }
    cpcommit();
}
#endif

__global__ __launch_bounds__(256, 1) void gemm1_hm() {
#if HM_OK
    extern __shared__ bf16 smh[];
    bf16* Ah  = smh;
    bf16* Al  = Ah  + 2 * BM * SROW;
    bf16* B1h = Al  + 2 * BM * SROW;
    bf16* B1l = B1h + 2 * HBN * SROW;
    bf16* B2h = B1l + 2 * HBN * SROW;
    bf16* B2l = B2h + 2 * HBN * SROW;

    int tile = blockIdx.y, nb0 = blockIdx.x * HBN;
    int e = gGrpE[tile >> 1];
    int tid = threadIdx.x, lane = tid & 31, warp = tid >> 5;
    int wm = warp & 3, wn = warp >> 2;
    int g = lane >> 2, t4 = lane & 3;

    const bf16* gAh  = gXh + (size_t)tile * BM * DIMV;
    const bf16* gAl  = gXl + (size_t)tile * BM * DIMV;
    const bf16* gB1h = gW1h + ((size_t)e * HIDV + nb0) * DIMV;
    const bf16* gB1l = gW1l + ((size_t)e * HIDV + nb0) * DIMV;
    const bf16* gB2h = gW2h + ((size_t)e * HIDV + nb0) * DIMV;
    const bf16* gB2l = gW2l + ((size_t)e * HIDV + nb0) * DIMV;

    float acc1[2][4][4], acc2[2][4][4];
#pragma unroll
    for (int m = 0; m < 2; m++)
#pragma unroll
        for (int n = 0; n < 4; n++)
#pragma unroll
            for (int i = 0; i < 4; i++) { acc1[m][n][i] = 0.f; acc2[m][n][i] = 0.f; }

    const int NSTEP = DIMV / BK;
    h1_load(Ah, Al, B1h, B1l, B2h, B2l, gAh, gAl, gB1h, gB1l, gB2h, gB2l, 0, tid);

    for (int s = 0; s < NSTEP; s++) {
        if (s + 1 < NSTEP) {
            int buf = (s + 1) & 1;
            h1_load(Ah + buf * BM * SROW, Al + buf * BM * SROW,
                    B1h + buf * HBN * SROW, B1l + buf * HBN * SROW,
                    B2h + buf * HBN * SROW, B2l + buf * HBN * SROW,
                    gAh, gAl, gB1h, gB1l, gB2h, gB2l, (s + 1) * BK, tid);
            asm volatile("cp.async.wait_group 1;\n");
        } else {
            asm volatile("cp.async.wait_group 0;\n");
        }
        __syncthreads();
        int buf = s & 1;
        const bf16* a_h = Ah  + buf * BM * SROW;
        const bf16* a_l = Al  + buf * BM * SROW;
        const bf16* b1h = B1h + buf * HBN * SROW;
        const bf16* b1l = B1l + buf * HBN * SROW;
        const bf16* b2h = B2h + buf * HBN * SROW;
        const bf16* b2l = B2l + buf * HBN * SROW;

#pragma unroll
        for (int kk = 0; kk < 2; kk++) {
            int kb = kk * 16;
            unsigned Afh[2][4], Afl[2][4];
#pragma unroll
            for (int mt = 0; mt < 2; mt++) {
                int rb = wm * 32 + mt * 16 + g;
                const bf16* p = a_h + rb * SROW + kb + t4 * 2;
                Afh[mt][0] = *(const unsigned*)(p);
                Afh[mt][1] = *(const unsigned*)(p + 8 * SROW);
                Afh[mt][2] = *(const unsigned*)(p + 8);
                Afh[mt][3] = *(const unsigned*)(p + 8 * SROW + 8);
                const bf16* q = a_l + rb * SROW + kb + t4 * 2;
                Afl[mt][0] = *(const unsigned*)(q);
                Afl[mt][1] = *(const unsigned*)(q + 8 * SROW);
                Afl[mt][2] = *(const unsigned*)(q + 8);
                Afl[mt][3] = *(const unsigned*)(q + 8 * SROW + 8);
            }
            {
                unsigned Bh[4][2], Bl[4][2];
#pragma unroll
                for (int nt = 0; nt < 4; nt++) {
                    int nr = wn * 32 + nt * 8 + g;
                    const bf16* p = b1h + nr * SROW + kb + t4 * 2;
                    Bh[nt][0] = *(const unsigned*)(p);
                    Bh[nt][1] = *(const unsigned*)(p + 8);
                    const bf16* q = b1l + nr * SROW + kb + t4 * 2;
                    Bl[nt][0] = *(const unsigned*)(q);
                    Bl[nt][1] = *(const unsigned*)(q + 8);
                }
#pragma unroll
                for (int mt = 0; mt < 2; mt++)
#pragma unroll
                    for (int nt = 0; nt < 4; nt++) {
                        mma_bf16(acc1[mt][nt], Afh[mt], Bh[nt]);
                        mma_bf16(acc1[mt][nt], Afh[mt], Bl[nt]);
                        mma_bf16(acc1[mt][nt], Afl[mt], Bh[nt]);
                    }
            }
            {
                unsigned Bh[4][2], Bl[4][2];
#pragma unroll
                for (int nt = 0; nt < 4; nt++) {
                    int nr = wn * 32 + nt * 8 + g;
                    const bf16* p = b2h + nr * SROW + kb + t4 * 2;
                    Bh[nt][0] = *(const unsigned*)(p);
                    Bh[nt][1] = *(const unsigned*)(p + 8);
                    const bf16* q = b2l + nr * SROW + kb + t4 * 2;
                    Bl[nt][0] = *(const unsigned*)(q);
                    Bl[nt][1] = *(const unsigned*)(q + 8);
                }
#pragma unroll
                for (int mt = 0; mt < 2; mt++)
#pragma unroll
                    for (int nt = 0; nt < 4; nt++) {
                        mma_bf16(acc2[mt][nt], Afh[mt], Bh[nt]);
                        mma_bf16(acc2[mt][nt], Afh[mt], Bl[nt]);
                        mma_bf16(acc2[mt][nt], Afl[mt], Bh[nt]);
                    }
            }
        }
        __syncthreads();
    }

#pragma unroll
    for (int mt = 0; mt < 2; mt++) {
#pragma unroll
        for (int nt = 0; nt < 4; nt++) {
            int lr = wm * 32 + mt * 16 + g;
            int grow = tile * 128 + lr;
            int col = nb0 + wn * 32 + nt * 8 + t4 * 2;
            const float* c1 = acc1[mt][nt];
            const float* c2 = acc2[mt][nt];
#pragma unroll
            for (int half = 0; half < 2; half++) {
                int r = grow + half * 8;
                float h1a = c1[half * 2 + 0], h1b = c1[half * 2 + 1];
                float h2a = c2[half * 2 + 0], h2b = c2[half * 2 + 1];
                float ua = h1a * (1.f / (1.f + expf(-h1a))) * h2a;
                float ub = h1b * (1.f / (1.f + expf(-h1b))) * h2b;
                bf16 ha, la, hb, lb;
                split2(ua, ha, la);
                split2(ub, hb, lb);
                __nv_bfloat162 vh; vh.x = ha; vh.y = hb;
                __nv_bfloat162 vl; vl.x = la; vl.y = lb;
                *(__nv_bfloat162*)(gUh + (size_t)r * HIDV + col) = vh;
                *(__nv_bfloat162*)(gUl + (size_t)r * HIDV + col) = vl;
            }
        }
    }
#endif
}

#if HM_OK
__device__ __forceinline__ void h2_load(
    bf16* a_h, bf16* a_l, bf16* bh, bf16* bl,
    const bf16* gAh, const bf16* gAl, const bf16* gBh, const bf16* gBl,
    int kc, int tid)
{
#pragma unroll
    for (int i = 0; i < 2; i++) {
        int q = tid * 2 + i, r = q >> 2, ko = (q & 3) * 8;
        size_t go = (size_t)r * HIDV + kc + ko;
        cp16(smem_u32(a_h + r * SROW + ko), gAh + go);
        cp16(smem_u32(a_l + r * SROW + ko), gAl + go);
    }
    {
        int r = tid >> 2, ko = (tid & 3) * 8;
        size_t go = (size_t)r * HIDV + kc + ko;
        cp16(smem_u32(bh + r * SROW + ko), gBh + go);
        cp16(smem_u32(bl + r * SROW + ko), gBl + go);
    }
    cpcommit();
}
#endif

__global__ __launch_bounds__(256, 1) void gemm2_hm(float* __restrict__ out) {
#if HM_OK
    extern __shared__ bf16 smh[];
    bf16* Ah = smh;
    bf16* Al = Ah + 2 * BM * SROW;
    bf16* Bh = Al + 2 * BM * SROW;
    bf16* Bl = Bh + 2 * HBN * SROW;

    int tile = blockIdx.y, nb0 = blockIdx.x * HBN;
    int e = gGrpE[tile >> 1];
    int tid = threadIdx.x, lane = tid & 31, warp = tid >> 5;
    int wm = warp & 3, wn = warp >> 2;
    int g = lane >> 2, t4 = lane & 3;

    const bf16* gAh2 = gUh + (size_t)tile * BM * HIDV;
    const bf16* gAl2 = gUl + (size_t)tile * BM * HIDV;
    const bf16* gBh2 = gW3h + ((size_t)e * DIMV + nb0) * HIDV;
    const bf16* gBl2 = gW3l + ((size_t)e * DIMV + nb0) * HIDV;

    float acc[2][4][4];
#pragma unroll
    for (int m = 0; m < 2; m++)
#pragma unroll
        for (int n = 0; n < 4; n++)
#pragma unroll
            for (int i = 0; i < 4; i++) acc[m][n][i] = 0.f;

    const int NSTEP = HIDV / BK;
    h2_load(Ah, Al, Bh, Bl, gAh2, gAl2, gBh2, gBl2, 0, tid);

    for (int s = 0; s < NSTEP; s++) {
        if (s + 1 < NSTEP) {
            int buf = (s + 1) & 1;
            h2_load(Ah + buf * BM * SROW, Al + buf * BM * SROW,
                    Bh + buf * HBN * SROW, Bl + buf * HBN * SROW,
                    gAh2, gAl2, gBh2, gBl2, (s + 1) * BK, tid);
            asm volatile("cp.async.wait_group 1;\n");
        } else {
            asm volatile("cp.async.wait_group 0;\n");
        }
        __syncthreads();
        int buf = s & 1;
        const bf16* a_h = Ah + buf * BM * SROW;
        const bf16* a_l = Al + buf * BM * SROW;
        const bf16* b_h = Bh + buf * HBN * SROW;
        const bf16* b_l = Bl + buf * HBN * SROW;

#pragma unroll
        for (int kk = 0; kk < 2; kk++) {
            int kb = kk * 16;
            unsigned Afh[2][4], Afl[2][4];
#pragma unroll
            for (int mt = 0; mt < 2; mt++) {
                int rb = wm * 32 + mt * 16 + g;
                const bf16* p = a_h + rb * SROW + kb + t4 * 2;
                Afh[mt][0] = *(const unsigned*)(p);
                Afh[mt][1] = *(const unsigned*)(p + 8 * SROW);
                Afh[mt][2] = *(const unsigned*)(p + 8);
                Afh[mt][3] = *(const unsigned*)(p + 8 * SROW + 8);
                const bf16* q = a_l + rb * SROW + kb + t4 * 2;
                Afl[mt][0] = *(const unsigned*)(q);
                Afl[mt][1] = *(const unsigned*)(q + 8 * SROW);
                Afl[mt][2] = *(const unsigned*)(q + 8);
                Afl[mt][3] = *(const unsigned*)(q + 8 * SROW + 8);
            }
            unsigned Bfh[4][2], Bfl[4][2];
#pragma unroll
            for (int nt = 0; nt < 4; nt++) {
                int nr = wn * 32 + nt * 8 + g;
                const bf16* p = b_h + nr * SROW + kb + t4 * 2;
                Bfh[nt][0] = *(const unsigned*)(p);
                Bfh[nt][1] = *(const unsigned*)(p + 8);
                const bf16* q = b_l + nr * SROW + kb + t4 * 2;
                Bfl[nt][0] = *(const unsigned*)(q);
                Bfl[nt][1] = *(const unsigned*)(q + 8);
            }
#pragma unroll
            for (int mt = 0; mt < 2; mt++)
#pragma unroll
                for (int nt = 0; nt < 4; nt++) {
                    mma_bf16(acc[mt][nt], Afh[mt], Bfh[nt]);
                    mma_bf16(acc[mt][nt], Afh[mt], Bfl[nt]);
                    mma_bf16(acc[mt][nt], Afl[mt], Bfh[nt]);
                }
        }
        __syncthreads();
    }

#pragma unroll
    for (int mt = 0; mt < 2; mt++) {
        int lr = wm * 32 + mt * 16 + g;
        int grow = tile * 128 + lr;
        int tokA = gRowTok[grow];
        int tokB = gRowTok[grow + 8];
        float pA = (tokA >= 0) ? gP[tokA] : 0.f;
        float pB = (tokB >= 0) ? gP[tokB] : 0.f;
#pragma unroll
        for (int nt = 0; nt < 4; nt++) {
            int col = nb0 + wn * 32 + nt * 8 + t4 * 2;
            const float* c = acc[mt][nt];
            if (tokA >= 0) {
                out[(size_t)tokA * DIMV + col]     = __bfloat162float(__float2bfloat16(c[0])) * pA;
                out[(size_t)tokA * DIMV + col + 1] = __bfloat162float(__float2bfloat16(c[1])) * pA;
            }
            if (tokB >= 0) {
                out[(size_t)tokB * DIMV + col]     = __bfloat162float(__float2bfloat16(c[2])) * pB;
                out[(size_t)tokB * DIMV + col + 1] = __bfloat162float(__float2bfloat16(c[3])) * pB;
            }
        }
    }
#endif
}

// ------------------------- launcher ----------------------------------------
extern "C" void kernel_launch(void* const* d_in, const int* in_sizes, int n_in,
                              void* d_out, int out_size) {
    const float* x  = (const float*)d_in[0];
    const float* rw = (const float*)d_in[1];
    const float* rb = (const float*)d_in[2];
    const float* w1 = (const float*)d_in[3];
    const float* w2 = (const float*)d_in[4];
    const float* w3 = (const float*)d_in[5];
    float* out = (float*)d_out;

    const int SH1 = (int)((2 * BM * SROW * 2 + 2 * HBN * SROW * 4) * sizeof(bf16));
    const int SH2 = (int)((2 * BM * SROW * 2 + 2 * HBN * SROW * 2) * sizeof(bf16));
    cudaFuncSetAttribute(gemm1_tc, cudaFuncAttributeMaxDynamicSharedMemorySize, G1_SMEM);
    cudaFuncSetAttribute(gemm2_tc, cudaFuncAttributeMaxDynamicSharedMemorySize, G2_SMEM);
    cudaFuncSetAttribute(gemm1_hm, cudaFuncAttributeMaxDynamicSharedMemorySize, SH1);
    cudaFuncSetAttribute(gemm2_hm, cudaFuncAttributeMaxDynamicSharedMemorySize, SH2);

    // gemm1_tc is our launch #4; with the harness's d_out-poison launch ahead
    // of us it should land on ncu's process-launch index 5 (-s 5 -c 1).
    router_k<<<TOKV / 8, 256>>>(x, rw, rb);                              // 0
    plan_k<<<1, 512>>>();                                                // 1
    gather_k<<<MAXROWS, 256>>>(x);                                       // 2
    tsplit12_k<<<dim3(HIDV / 64, DIMV / 64, 2 * NEXP), 256>>>(w1, w2);   // 3
    gemm1_tc<<<dim3(HIDV / 128, MAXGRP), 256, G1_SMEM>>>();              // 4
    gemm1_hm<<<dim3(HIDV / HBN, NTILE), 256, SH1>>>();                   // 5
    tsplit3_k<<<dim3(DIMV / 64, HIDV / 64, NEXP), 256>>>(w3);            // 6
    gemm2_tc<<<dim3(DIMV / 128, MAXGRP), 256, G2_SMEM>>>(out);           // 7
    gemm2_hm<<<dim3(DIMV / HBN, NTILE), 256, SH2>>>(out);                // 8
}